// round 15
// baseline (speedup 1.0000x reference)
#include <cuda_runtime.h>
#include <cuda_bf16.h>

// ---------------------------------------------------------------------------
// GaussianVoxelizer round 12 = round-10 chassis + survivor-pair pipelining
//   k_prepbin: warp/gaussian, lane0 math, lane-per-tile-slot atomics (8^3 tiles)
//   k_main:    block(256) per 8x8x8 tile; warp owns 4x4x4 cell; thread = 2
//              contiguous z voxels. Ballot-compacted survivor list; survivors
//              processed in PAIRS (two independent weight chains + interleaved
//              FMA streams) to hide LDS/MUFU latency at low occupancy.
// ---------------------------------------------------------------------------

#define NG      8192
#define HN      160
#define WN      160
#define DN      16
#define VSZ     0.4f
#define VMX     (-32.0f)
#define VMY     (-32.0f)
#define VMZ     (-1.0f)

#define TSH     3
#define TXN     (HN >> TSH)         // 20
#define TYN     (WN >> TSH)         // 20
#define TZN     (DN >> TSH)         // 2
#define NTILES  (TXN * TYN * TZN)   // 800

#define TCAP    256
#define CCHUNK  128
#define KEXP2   0.72134752044448170f   // 0.5 * log2(e)
#define CHALF   (1.5f * VSZ + 1e-4f)   // 4x4x4 cell half-extent (voxel centers)

__device__ float g_params[NG * 16];
__device__ int   g_cnt[NTILES];        // zero-init at load; k_main re-zeros
__device__ int   g_list[NTILES * TCAP];

__device__ __forceinline__ float ex2(float x) {
    float r;
    asm("ex2.approx.f32 %0, %1;" : "=f"(r) : "f"(x));
    return r;
}

// ---------------------------------------------------------------------------
__global__ void k_prepbin(const float* __restrict__ means,
                          const float* __restrict__ opac,
                          const float* __restrict__ scl,
                          const float* __restrict__ rot) {
    int t = blockIdx.x * blockDim.x + threadIdx.x;
    int g = t >> 5, lane = t & 31;
    if (g >= NG) return;

    unsigned range = 0xFFFFFFFFu;
    if (lane == 0) {
        float qw = rot[4 * g + 0], qx = rot[4 * g + 1];
        float qy = rot[4 * g + 2], qz = rot[4 * g + 3];
        float qn = rsqrtf(qw * qw + qx * qx + qy * qy + qz * qz);
        qw *= qn; qx *= qn; qy *= qn; qz *= qn;

        float r00 = 1.f - 2.f * (qy * qy + qz * qz);
        float r01 = 2.f * (qx * qy - qw * qz);
        float r02 = 2.f * (qx * qz + qw * qy);
        float r10 = 2.f * (qx * qy + qw * qz);
        float r11 = 1.f - 2.f * (qx * qx + qz * qz);
        float r12 = 2.f * (qy * qz - qw * qx);
        float r20 = 2.f * (qx * qz - qw * qy);
        float r21 = 2.f * (qy * qz + qw * qx);
        float r22 = 1.f - 2.f * (qx * qx + qy * qy);

        float s0 = scl[3 * g + 0], s1 = scl[3 * g + 1], s2 = scl[3 * g + 2];
        float v0 = s0 * s0, v1 = s1 * s1, v2 = s2 * s2;
        float a0 = 1.f / v0, a1 = 1.f / v1, a2 = 1.f / v2;

        float i00 = (r00 * r00 * a0 + r01 * r01 * a1 + r02 * r02 * a2) * KEXP2;
        float i01 = (r00 * r10 * a0 + r01 * r11 * a1 + r02 * r12 * a2) * KEXP2;
        float i02 = (r00 * r20 * a0 + r01 * r21 * a1 + r02 * r22 * a2) * KEXP2;
        float i11 = (r10 * r10 * a0 + r11 * r11 * a1 + r12 * r12 * a2) * KEXP2;
        float i12 = (r10 * r20 * a0 + r11 * r21 * a1 + r12 * r22 * a2) * KEXP2;
        float i22 = (r20 * r20 * a0 + r21 * r21 * a1 + r22 * r22 * a2) * KEXP2;

        float c00 = r00 * r00 * v0 + r01 * r01 * v1 + r02 * r02 * v2;
        float c11 = r10 * r10 * v0 + r11 * r11 * v1 + r12 * r12 * v2;
        float c22 = r20 * r20 * v0 + r21 * r21 * v1 + r22 * r22 * v2;
        float bx = 3.f * sqrtf(c00);
        float by = 3.f * sqrtf(c11);
        float bz = 3.f * sqrtf(c22);

        float mx = means[3 * g + 0], my = means[3 * g + 1], mz = means[3 * g + 2];
        float op = opac[g];

        float4* p4 = (float4*)&g_params[g * 16];
        p4[0] = make_float4(mx, my, mz, op);
        p4[1] = make_float4(bx, by, bz, 0.f);
        p4[2] = make_float4(i00, i01, i02, i11);
        p4[3] = make_float4(i12, i22, 0.f, 0.f);

        float mu[3] = { mx, my, mz };
        float bb[3] = { bx, by, bz };
        const float vmin[3] = { VMX, VMY, VMZ };
        const int nd[3] = { HN, WN, DN };
        int lo[3], hi[3];
        bool ok = true;
#pragma unroll
        for (int d = 0; d < 3; d++) {
            float l = (mu[d] - bb[d] - vmin[d]) / VSZ - 0.5f;
            float h = (mu[d] + bb[d] - vmin[d]) / VSZ - 0.5f;
            int i0 = (int)ceilf(l - 1e-3f);  if (i0 < 0) i0 = 0;
            int i1 = (int)floorf(h + 1e-3f); if (i1 > nd[d] - 1) i1 = nd[d] - 1;
            if (i0 > i1) ok = false;
            lo[d] = i0 >> TSH; hi[d] = i1 >> TSH;
        }
        if (ok)
            range = (unsigned)lo[0] | ((unsigned)hi[0] << 5)
                  | ((unsigned)lo[1] << 10) | ((unsigned)hi[1] << 15)
                  | ((unsigned)lo[2] << 20) | ((unsigned)hi[2] << 25);
    }
    range = __shfl_sync(0xffffffffu, range, 0);
    if (range == 0xFFFFFFFFu) return;

    int x0 = range & 31, x1 = (range >> 5) & 31;
    int y0 = (range >> 10) & 31, y1 = (range >> 15) & 31;
    int z0 = (range >> 20) & 31, z1 = (range >> 25) & 31;
    int nx = x1 - x0 + 1, ny = y1 - y0 + 1, nz = z1 - z0 + 1;
    if (lane >= nx * ny * nz) return;       // max span 3*3*2 = 18 <= 32
    int sz = lane % nz; int rem = lane / nz;
    int sy = rem % ny;  int sx = rem / ny;
    int tile = ((x0 + sx) * TYN + (y0 + sy)) * TZN + (z0 + sz);
    int pos = atomicAdd(&g_cnt[tile], 1);
    if (pos < TCAP) g_list[tile * TCAP + pos] = g;
}

// ---------------------------------------------------------------------------
__global__ __launch_bounds__(256, 2)
void k_main(const float* __restrict__ feat, float* __restrict__ out) {
    __shared__ int    s_idx[CCHUNK];
    __shared__ float4 s_par[CCHUNK * 4];
    __shared__ float4 s_fea[CCHUNK * 8];
    __shared__ int    s_surv[8][CCHUNK];
    __shared__ int    s_n;

    int bt = blockIdx.x;
    int tz = bt % TZN;
    int ty = (bt / TZN) % TYN;
    int tx = bt / (TZN * TYN);

    int tid  = threadIdx.x;
    int w    = tid >> 5;
    int lane = tid & 31;
    int wx = w & 1, wy = (w >> 1) & 1, wz = (w >> 2) & 1;
    int lz2 = lane & 1;
    int ly  = (lane >> 1) & 3;
    int lx  = (lane >> 3) & 3;

    int vib = (tx << TSH) + (wx << 2);     // warp cell voxel bases
    int vjb = (ty << TSH) + (wy << 2);
    int vkb = (tz << TSH) + (wz << 2);

    int vi = vib + lx;
    int vj = vjb + ly;
    int vk = vkb + (lz2 << 1);

    float px  = ((float)vi + 0.5f) * VSZ + VMX;
    float py  = ((float)vj + 0.5f) * VSZ + VMY;
    float pz0 = ((float)vk + 0.5f) * VSZ + VMZ;
    float pz1 = pz0 + VSZ;

    // warp cell centers (voxel-center span is +/- 1.5*VSZ around these)
    float ccx = ((float)vib + 2.0f) * VSZ + VMX;
    float ccy = ((float)vjb + 2.0f) * VSZ + VMY;
    float ccz = ((float)vkb + 2.0f) * VSZ + VMZ;

    int tile = (tx * TYN + ty) * TZN + tz;
    if (tid == 0) {
        int nn = g_cnt[tile];
        g_cnt[tile] = 0;                   // reset for next graph replay
        s_n = nn;
    }

    float4 a0[8], a1[8];
#pragma unroll
    for (int r = 0; r < 8; r++) {
        a0[r] = make_float4(0.f, 0.f, 0.f, 0.f);
        a1[r] = make_float4(0.f, 0.f, 0.f, 0.f);
    }

    __syncthreads();
    int n = min(s_n, TCAP);

    const float4* gp4 = (const float4*)g_params;
    const float4* gf4 = (const float4*)feat;

    for (int base = 0; base < n; base += CCHUNK) {
        int cnt = min(CCHUNK, n - base);
        __syncthreads();
        if (tid < cnt) s_idx[tid] = g_list[tile * TCAP + base + tid];
        __syncthreads();
        for (int u = tid; u < cnt * 4; u += 256) {
            int c = u >> 2, pc = u & 3;
            s_par[u] = gp4[s_idx[c] * 4 + pc];
        }
        for (int u = tid; u < cnt * 8; u += 256) {
            int c = u >> 3, pc = u & 7;
            s_fea[u] = gf4[s_idx[c] * 8 + pc];
        }
        __syncthreads();

        // ---- phase 1: lane-parallel cell-vs-box test, ballot compaction ----
        int nsurv = 0;
        for (int b2 = 0; b2 < cnt; b2 += 32) {
            int c = b2 + lane;
            bool ov = false;
            if (c < cnt) {
                float4 p0 = s_par[c * 4 + 0];
                float4 p1 = s_par[c * 4 + 1];
                ov = (fabsf(ccx - p0.x) <= p1.x + CHALF)
                  && (fabsf(ccy - p0.y) <= p1.y + CHALF)
                  && (fabsf(ccz - p0.z) <= p1.z + CHALF);
            }
            unsigned m = __ballot_sync(0xffffffffu, ov);
            if (ov)
                s_surv[w][nsurv + __popc(m & ((1u << lane) - 1u))] = c;
            nsurv += __popc(m);
        }
        __syncwarp();

        // ---- phase 2: survivor PAIRS — two independent weight chains ----
        int s = 0;
        for (; s + 2 <= nsurv; s += 2) {
            int ca = s_surv[w][s];
            int cb = s_surv[w][s + 1];
            float4 A0 = s_par[ca * 4 + 0], B0 = s_par[cb * 4 + 0];
            float4 A1 = s_par[ca * 4 + 1], B1 = s_par[cb * 4 + 1];
            float4 A2 = s_par[ca * 4 + 2], B2 = s_par[cb * 4 + 2];
            float4 A3 = s_par[ca * 4 + 3], B3 = s_par[cb * 4 + 3];

            float adx = px - A0.x, ady = py - A0.y;
            float adz0 = pz0 - A0.z, adz1 = pz1 - A0.z;
            float bdx = px - B0.x, bdy = py - B0.y;
            float bdz0 = pz0 - B0.z, bdz1 = pz1 - B0.z;

            bool ainxy = (fabsf(adx) <= A1.x) && (fabsf(ady) <= A1.y);
            bool binxy = (fabsf(bdx) <= B1.x) && (fabsf(bdy) <= B1.y);
            bool ain0 = ainxy && (fabsf(adz0) <= A1.z);
            bool ain1 = ainxy && (fabsf(adz1) <= A1.z);
            bool bin0 = binxy && (fabsf(bdz0) <= B1.z);
            bool bin1 = binxy && (fabsf(bdz1) <= B1.z);

            float amb = adx * (A2.x * adx + 2.f * A2.y * ady) + A2.w * ady * ady;
            float bmb = bdx * (B2.x * bdx + 2.f * B2.y * bdy) + B2.w * bdy * bdy;
            float acz = 2.f * (A2.z * adx + A3.x * ady);
            float bcz = 2.f * (B2.z * bdx + B3.x * bdy);
            float am0 = amb + adz0 * (A3.y * adz0 + acz);
            float am1 = amb + adz1 * (A3.y * adz1 + acz);
            float bm0 = bmb + bdz0 * (B3.y * bdz0 + bcz);
            float bm1 = bmb + bdz1 * (B3.y * bdz1 + bcz);

            float wa0 = ain0 ? A0.w * ex2(-am0) : 0.f;
            float wa1 = ain1 ? A0.w * ex2(-am1) : 0.f;
            float wb0 = bin0 ? B0.w * ex2(-bm0) : 0.f;
            float wb1 = bin1 ? B0.w * ex2(-bm1) : 0.f;

            const float4* fa = &s_fea[ca * 8];
            const float4* fb = &s_fea[cb * 8];
#pragma unroll
            for (int r = 0; r < 8; r++) {
                float4 va = fa[r];
                float4 vb = fb[r];
                a0[r].x += wa0 * va.x + wb0 * vb.x;
                a0[r].y += wa0 * va.y + wb0 * vb.y;
                a0[r].z += wa0 * va.z + wb0 * vb.z;
                a0[r].w += wa0 * va.w + wb0 * vb.w;
                a1[r].x += wa1 * va.x + wb1 * vb.x;
                a1[r].y += wa1 * va.y + wb1 * vb.y;
                a1[r].z += wa1 * va.z + wb1 * vb.z;
                a1[r].w += wa1 * va.w + wb1 * vb.w;
            }
        }
        // tail survivor
        if (s < nsurv) {
            int c = s_surv[w][s];
            float4 p0 = s_par[c * 4 + 0];
            float4 p1 = s_par[c * 4 + 1];
            float4 p2 = s_par[c * 4 + 2];
            float4 p3 = s_par[c * 4 + 3];
            float dx = px - p0.x, dy = py - p0.y;
            float dz0 = pz0 - p0.z, dz1 = pz1 - p0.z;
            bool inxy = (fabsf(dx) <= p1.x) && (fabsf(dy) <= p1.y);
            bool in0 = inxy && (fabsf(dz0) <= p1.z);
            bool in1 = inxy && (fabsf(dz1) <= p1.z);
            float mb = dx * (p2.x * dx + 2.f * p2.y * dy) + p2.w * dy * dy;
            float cz = 2.f * (p2.z * dx + p3.x * dy);
            float m0 = mb + dz0 * (p3.y * dz0 + cz);
            float m1 = mb + dz1 * (p3.y * dz1 + cz);
            float w0 = in0 ? p0.w * ex2(-m0) : 0.f;
            float w1 = in1 ? p0.w * ex2(-m1) : 0.f;
            const float4* f = &s_fea[c * 8];
#pragma unroll
            for (int r = 0; r < 8; r++) {
                float4 fv = f[r];
                a0[r].x += w0 * fv.x; a0[r].y += w0 * fv.y;
                a0[r].z += w0 * fv.z; a0[r].w += w0 * fv.w;
                a1[r].x += w1 * fv.x; a1[r].y += w1 * fv.y;
                a1[r].z += w1 * fv.z; a1[r].w += w1 * fv.w;
            }
        }
    }

    // thread writes 2 contiguous voxels: 256B
    long long v = ((long long)vi * WN + vj) * DN + vk;
    float4* o0 = (float4*)(out + v * 32);
    float4* o1 = (float4*)(out + (v + 1) * 32);
#pragma unroll
    for (int r = 0; r < 8; r++) o0[r] = a0[r];
#pragma unroll
    for (int r = 0; r < 8; r++) o1[r] = a1[r];
}

// ---------------------------------------------------------------------------
extern "C" void kernel_launch(void* const* d_in, const int* in_sizes, int n_in,
                              void* d_out, int out_size) {
    const float* means = (const float*)d_in[0];
    const float* opac  = (const float*)d_in[1];
    const float* scl   = (const float*)d_in[2];
    const float* rot   = (const float*)d_in[3];
    const float* feat  = (const float*)d_in[4];
    float* out = (float*)d_out;

    k_prepbin<<<(NG * 32 + 255) / 256, 256>>>(means, opac, scl, rot);
    k_main<<<NTILES, 256>>>(feat, out);
}

// round 16
// speedup vs baseline: 1.0474x; 1.0474x over previous
#include <cuda_runtime.h>
#include <cuda_bf16.h>

// ---------------------------------------------------------------------------
// GaussianVoxelizer round 15 = R10 chassis + depth-4 split-phase pipelining
//                              + persistent work-stealing blocks
//   k_prepbin: warp/gaussian, lane0 math, lane-per-slot atomics; resets work ctr
//   k_main:    296 persistent blocks; each steals 8x8x8 tiles from a counter.
//              Warp owns 4x4x4 cell; thread = 2 contiguous z voxels.
//              Ballot-compacted survivors; weight chains computed 4-at-a-time
//              (independent, latency-covering), then a pure LDS+FFMA phase.
// ---------------------------------------------------------------------------

#define NG      8192
#define HN      160
#define WN      160
#define DN      16
#define VSZ     0.4f
#define VMX     (-32.0f)
#define VMY     (-32.0f)
#define VMZ     (-1.0f)

#define TSH     3
#define TXN     (HN >> TSH)         // 20
#define TYN     (WN >> TSH)         // 20
#define TZN     (DN >> TSH)         // 2
#define NTILES  (TXN * TYN * TZN)   // 800

#define TCAP    256
#define CCHUNK  128
#define NBLK    296                 // 148 SMs x 2 blocks
#define KEXP2   0.72134752044448170f   // 0.5 * log2(e)
#define CHALF   (1.5f * VSZ + 1e-4f)   // 4x4x4 cell half-extent (voxel centers)

__device__ float g_params[NG * 16];
__device__ int   g_cnt[NTILES];        // zero-init at load; k_main re-zeros
__device__ int   g_list[NTILES * TCAP];
__device__ int   g_work;               // tile work counter (reset by k_prepbin)

__device__ __forceinline__ float ex2(float x) {
    float r;
    asm("ex2.approx.f32 %0, %1;" : "=f"(r) : "f"(x));
    return r;
}

// ---------------------------------------------------------------------------
__global__ void k_prepbin(const float* __restrict__ means,
                          const float* __restrict__ opac,
                          const float* __restrict__ scl,
                          const float* __restrict__ rot) {
    int t = blockIdx.x * blockDim.x + threadIdx.x;
    if (t == 0) g_work = 0;            // reset work counter for k_main
    int g = t >> 5, lane = t & 31;
    if (g >= NG) return;

    unsigned range = 0xFFFFFFFFu;
    if (lane == 0) {
        float qw = rot[4 * g + 0], qx = rot[4 * g + 1];
        float qy = rot[4 * g + 2], qz = rot[4 * g + 3];
        float qn = rsqrtf(qw * qw + qx * qx + qy * qy + qz * qz);
        qw *= qn; qx *= qn; qy *= qn; qz *= qn;

        float r00 = 1.f - 2.f * (qy * qy + qz * qz);
        float r01 = 2.f * (qx * qy - qw * qz);
        float r02 = 2.f * (qx * qz + qw * qy);
        float r10 = 2.f * (qx * qy + qw * qz);
        float r11 = 1.f - 2.f * (qx * qx + qz * qz);
        float r12 = 2.f * (qy * qz - qw * qx);
        float r20 = 2.f * (qx * qz - qw * qy);
        float r21 = 2.f * (qy * qz + qw * qx);
        float r22 = 1.f - 2.f * (qx * qx + qy * qy);

        float s0 = scl[3 * g + 0], s1 = scl[3 * g + 1], s2 = scl[3 * g + 2];
        float v0 = s0 * s0, v1 = s1 * s1, v2 = s2 * s2;
        float a0 = 1.f / v0, a1 = 1.f / v1, a2 = 1.f / v2;

        float i00 = (r00 * r00 * a0 + r01 * r01 * a1 + r02 * r02 * a2) * KEXP2;
        float i01 = (r00 * r10 * a0 + r01 * r11 * a1 + r02 * r12 * a2) * KEXP2;
        float i02 = (r00 * r20 * a0 + r01 * r21 * a1 + r02 * r22 * a2) * KEXP2;
        float i11 = (r10 * r10 * a0 + r11 * r11 * a1 + r12 * r12 * a2) * KEXP2;
        float i12 = (r10 * r20 * a0 + r11 * r21 * a1 + r12 * r22 * a2) * KEXP2;
        float i22 = (r20 * r20 * a0 + r21 * r21 * a1 + r22 * r22 * a2) * KEXP2;

        float c00 = r00 * r00 * v0 + r01 * r01 * v1 + r02 * r02 * v2;
        float c11 = r10 * r10 * v0 + r11 * r11 * v1 + r12 * r12 * v2;
        float c22 = r20 * r20 * v0 + r21 * r21 * v1 + r22 * r22 * v2;
        float bx = 3.f * sqrtf(c00);
        float by = 3.f * sqrtf(c11);
        float bz = 3.f * sqrtf(c22);

        float mx = means[3 * g + 0], my = means[3 * g + 1], mz = means[3 * g + 2];
        float op = opac[g];

        float4* p4 = (float4*)&g_params[g * 16];
        p4[0] = make_float4(mx, my, mz, op);
        p4[1] = make_float4(bx, by, bz, 0.f);
        p4[2] = make_float4(i00, i01, i02, i11);
        p4[3] = make_float4(i12, i22, 0.f, 0.f);

        float mu[3] = { mx, my, mz };
        float bb[3] = { bx, by, bz };
        const float vmin[3] = { VMX, VMY, VMZ };
        const int nd[3] = { HN, WN, DN };
        int lo[3], hi[3];
        bool ok = true;
#pragma unroll
        for (int d = 0; d < 3; d++) {
            float l = (mu[d] - bb[d] - vmin[d]) / VSZ - 0.5f;
            float h = (mu[d] + bb[d] - vmin[d]) / VSZ - 0.5f;
            int i0 = (int)ceilf(l - 1e-3f);  if (i0 < 0) i0 = 0;
            int i1 = (int)floorf(h + 1e-3f); if (i1 > nd[d] - 1) i1 = nd[d] - 1;
            if (i0 > i1) ok = false;
            lo[d] = i0 >> TSH; hi[d] = i1 >> TSH;
        }
        if (ok)
            range = (unsigned)lo[0] | ((unsigned)hi[0] << 5)
                  | ((unsigned)lo[1] << 10) | ((unsigned)hi[1] << 15)
                  | ((unsigned)lo[2] << 20) | ((unsigned)hi[2] << 25);
    }
    range = __shfl_sync(0xffffffffu, range, 0);
    if (range == 0xFFFFFFFFu) return;

    int x0 = range & 31, x1 = (range >> 5) & 31;
    int y0 = (range >> 10) & 31, y1 = (range >> 15) & 31;
    int z0 = (range >> 20) & 31, z1 = (range >> 25) & 31;
    int nx = x1 - x0 + 1, ny = y1 - y0 + 1, nz = z1 - z0 + 1;
    if (lane >= nx * ny * nz) return;       // max span 3*3*2 = 18 <= 32
    int sz = lane % nz; int rem = lane / nz;
    int sy = rem % ny;  int sx = rem / ny;
    int tile = ((x0 + sx) * TYN + (y0 + sy)) * TZN + (z0 + sz);
    int pos = atomicAdd(&g_cnt[tile], 1);
    if (pos < TCAP) g_list[tile * TCAP + pos] = g;
}

// ---------------------------------------------------------------------------
__global__ __launch_bounds__(256, 2)
void k_main(const float* __restrict__ feat, float* __restrict__ out) {
    __shared__ int    s_idx[CCHUNK];
    __shared__ float4 s_par[CCHUNK * 4];
    __shared__ float4 s_fea[CCHUNK * 8];
    __shared__ int    s_surv[8][CCHUNK];
    __shared__ int    s_n;
    __shared__ int    s_tile;

    int tid  = threadIdx.x;
    int w    = tid >> 5;
    int lane = tid & 31;
    int wx = w & 1, wy = (w >> 1) & 1, wz = (w >> 2) & 1;
    int lz2 = lane & 1;
    int ly  = (lane >> 1) & 3;
    int lx  = (lane >> 3) & 3;

    const float4* gp4 = (const float4*)g_params;
    const float4* gf4 = (const float4*)feat;

    for (;;) {
        // ---- steal a tile ----
        if (tid == 0) {
            int t = atomicAdd(&g_work, 1);
            s_tile = t;
            if (t < NTILES) {
                s_n = g_cnt[t];
                g_cnt[t] = 0;              // reset for next graph replay
            }
        }
        __syncthreads();
        int tile = s_tile;
        if (tile >= NTILES) break;
        int n = min(s_n, TCAP);
        __syncthreads();                   // s_tile/s_n consumed before reuse

        int tz = tile % TZN;
        int ty = (tile / TZN) % TYN;
        int tx = tile / (TZN * TYN);

        int vib = (tx << TSH) + (wx << 2);
        int vjb = (ty << TSH) + (wy << 2);
        int vkb = (tz << TSH) + (wz << 2);

        int vi = vib + lx;
        int vj = vjb + ly;
        int vk = vkb + (lz2 << 1);

        float px  = ((float)vi + 0.5f) * VSZ + VMX;
        float py  = ((float)vj + 0.5f) * VSZ + VMY;
        float pz0 = ((float)vk + 0.5f) * VSZ + VMZ;
        float pz1 = pz0 + VSZ;

        float ccx = ((float)vib + 2.0f) * VSZ + VMX;
        float ccy = ((float)vjb + 2.0f) * VSZ + VMY;
        float ccz = ((float)vkb + 2.0f) * VSZ + VMZ;

        float4 a0[8], a1[8];
#pragma unroll
        for (int r = 0; r < 8; r++) {
            a0[r] = make_float4(0.f, 0.f, 0.f, 0.f);
            a1[r] = make_float4(0.f, 0.f, 0.f, 0.f);
        }

        for (int base = 0; base < n; base += CCHUNK) {
            int cnt = min(CCHUNK, n - base);
            __syncthreads();
            if (tid < cnt) s_idx[tid] = g_list[tile * TCAP + base + tid];
            __syncthreads();
            for (int u = tid; u < cnt * 4; u += 256) {
                int c = u >> 2, pc = u & 3;
                s_par[u] = gp4[s_idx[c] * 4 + pc];
            }
            for (int u = tid; u < cnt * 8; u += 256) {
                int c = u >> 3, pc = u & 7;
                s_fea[u] = gf4[s_idx[c] * 8 + pc];
            }
            __syncthreads();

            // ---- phase 1: cell-vs-box ballot compaction ----
            int nsurv = 0;
            for (int b2 = 0; b2 < cnt; b2 += 32) {
                int c = b2 + lane;
                bool ov = false;
                if (c < cnt) {
                    float4 p0 = s_par[c * 4 + 0];
                    float4 p1 = s_par[c * 4 + 1];
                    ov = (fabsf(ccx - p0.x) <= p1.x + CHALF)
                      && (fabsf(ccy - p0.y) <= p1.y + CHALF)
                      && (fabsf(ccz - p0.z) <= p1.z + CHALF);
                }
                unsigned m = __ballot_sync(0xffffffffu, ov);
                if (ov)
                    s_surv[w][nsurv + __popc(m & ((1u << lane) - 1u))] = c;
                nsurv += __popc(m);
            }
            __syncwarp();

            // ---- phase 2a+2b: depth-4 weight chains, then pure FMA ----
            int s = 0;
            for (; s + 4 <= nsurv; s += 4) {
                float w0v[4], w1v[4];
                int   cs[4];
#pragma unroll
                for (int j = 0; j < 4; j++) {
                    int c = s_surv[w][s + j];
                    cs[j] = c;
                    float4 p0 = s_par[c * 4 + 0];
                    float4 p1 = s_par[c * 4 + 1];
                    float4 p2 = s_par[c * 4 + 2];
                    float4 p3 = s_par[c * 4 + 3];
                    float dx = px - p0.x, dy = py - p0.y;
                    float dz0 = pz0 - p0.z, dz1 = pz1 - p0.z;
                    bool inxy = (fabsf(dx) <= p1.x) && (fabsf(dy) <= p1.y);
                    bool in0 = inxy && (fabsf(dz0) <= p1.z);
                    bool in1 = inxy && (fabsf(dz1) <= p1.z);
                    float mb = dx * (p2.x * dx + 2.f * p2.y * dy) + p2.w * dy * dy;
                    float cz = 2.f * (p2.z * dx + p3.x * dy);
                    float m0 = mb + dz0 * (p3.y * dz0 + cz);
                    float m1 = mb + dz1 * (p3.y * dz1 + cz);
                    w0v[j] = in0 ? p0.w * ex2(-m0) : 0.f;
                    w1v[j] = in1 ? p0.w * ex2(-m1) : 0.f;
                }
#pragma unroll
                for (int j = 0; j < 4; j++) {
                    const float4* f = &s_fea[cs[j] * 8];
                    float w0 = w0v[j], w1 = w1v[j];
#pragma unroll
                    for (int r = 0; r < 8; r++) {
                        float4 fv = f[r];
                        a0[r].x += w0 * fv.x; a0[r].y += w0 * fv.y;
                        a0[r].z += w0 * fv.z; a0[r].w += w0 * fv.w;
                        a1[r].x += w1 * fv.x; a1[r].y += w1 * fv.y;
                        a1[r].z += w1 * fv.z; a1[r].w += w1 * fv.w;
                    }
                }
            }
            // tail survivors (0-3)
            for (; s < nsurv; s++) {
                int c = s_surv[w][s];
                float4 p0 = s_par[c * 4 + 0];
                float4 p1 = s_par[c * 4 + 1];
                float4 p2 = s_par[c * 4 + 2];
                float4 p3 = s_par[c * 4 + 3];
                float dx = px - p0.x, dy = py - p0.y;
                float dz0 = pz0 - p0.z, dz1 = pz1 - p0.z;
                bool inxy = (fabsf(dx) <= p1.x) && (fabsf(dy) <= p1.y);
                bool in0 = inxy && (fabsf(dz0) <= p1.z);
                bool in1 = inxy && (fabsf(dz1) <= p1.z);
                float mb = dx * (p2.x * dx + 2.f * p2.y * dy) + p2.w * dy * dy;
                float cz = 2.f * (p2.z * dx + p3.x * dy);
                float m0 = mb + dz0 * (p3.y * dz0 + cz);
                float m1 = mb + dz1 * (p3.y * dz1 + cz);
                float w0 = in0 ? p0.w * ex2(-m0) : 0.f;
                float w1 = in1 ? p0.w * ex2(-m1) : 0.f;
                const float4* f = &s_fea[c * 8];
#pragma unroll
                for (int r = 0; r < 8; r++) {
                    float4 fv = f[r];
                    a0[r].x += w0 * fv.x; a0[r].y += w0 * fv.y;
                    a0[r].z += w0 * fv.z; a0[r].w += w0 * fv.w;
                    a1[r].x += w1 * fv.x; a1[r].y += w1 * fv.y;
                    a1[r].z += w1 * fv.z; a1[r].w += w1 * fv.w;
                }
            }
        }

        // thread writes 2 contiguous voxels: 256B
        long long v = ((long long)vi * WN + vj) * DN + vk;
        float4* o0 = (float4*)(out + v * 32);
        float4* o1 = (float4*)(out + (v + 1) * 32);
#pragma unroll
        for (int r = 0; r < 8; r++) o0[r] = a0[r];
#pragma unroll
        for (int r = 0; r < 8; r++) o1[r] = a1[r];
    }
}

// ---------------------------------------------------------------------------
extern "C" void kernel_launch(void* const* d_in, const int* in_sizes, int n_in,
                              void* d_out, int out_size) {
    const float* means = (const float*)d_in[0];
    const float* opac  = (const float*)d_in[1];
    const float* scl   = (const float*)d_in[2];
    const float* rot   = (const float*)d_in[3];
    const float* feat  = (const float*)d_in[4];
    float* out = (float*)d_out;

    k_prepbin<<<(NG * 32 + 255) / 256, 256>>>(means, opac, scl, rot);
    k_main<<<NBLK, 256>>>(feat, out);
}